// round 1
// baseline (speedup 1.0000x reference)
#include <cuda_runtime.h>
#include <math.h>
#include <stdint.h>

#define NN    8192
#define DIMM  512
#define DKK   128
#define DVV   512
#define NCHUNK 256
#define CHUNK  32

// ---------------- scratch (device globals; no allocation) ----------------
__device__ float  g_u1[DIMM], g_u2[DIMM];
__device__ double g_beta[2];
__device__ float  g_s[NN], g_d[NN];
__device__ float  g_D;
__device__ int    g_rank[NN];
__device__ float  g_sorted[NN];
__device__ float  g_P1[(size_t)NN * DVV];
__device__ float  g_P2[(size_t)NN * DVV];
__device__ float  g_S1[(size_t)(NN + 1) * DVV];
__device__ float  g_S2[(size_t)(NN + 1) * DVV];
__device__ float  g_cs1[NCHUNK * DVV], g_cs2[NCHUNK * DVV];
__device__ float  g_off1[NCHUNK * DVV], g_off2[NCHUNK * DVV];
__device__ float  g_zpre[NN + 1], g_zsuf[NN + 1];

// ---------------- f32x2 packed helpers ----------------
__device__ __forceinline__ unsigned long long pack2(float lo, float hi) {
    unsigned long long r;
    asm("mov.b64 %0, {%1, %2};" : "=l"(r) : "f"(lo), "f"(hi));
    return r;
}
__device__ __forceinline__ void unpack2(unsigned long long v, float& lo, float& hi) {
    asm("mov.b64 {%0, %1}, %2;" : "=f"(lo), "=f"(hi) : "l"(v));
}
__device__ __forceinline__ unsigned long long fma2(unsigned long long a,
                                                   unsigned long long b,
                                                   unsigned long long c) {
    unsigned long long d;
    asm("fma.rn.f32x2 %0, %1, %2, %3;" : "=l"(d) : "l"(a), "l"(b), "l"(c));
    return d;
}

// ---------------- K0: u1 = W^T a1, u2 = W^T a2, betas ----------------
__global__ void k_prep(const float* __restrict__ Ww, const float* __restrict__ wb,
                       const float* __restrict__ a) {
    int d = blockIdx.x * 256 + threadIdx.x;  // 0..511
    double s1 = 0.0, s2 = 0.0;
    for (int k = 0; k < DKK; k++) {
        double w = Ww[(size_t)k * DIMM + d];
        s1 += w * (double)a[k];
        s2 += w * (double)a[DKK + k];
    }
    g_u1[d] = (float)s1;
    g_u2[d] = (float)s2;
    if (d == 0) {
        double b1 = 0.0, b2 = 0.0;
        for (int k = 0; k < DKK; k++) {
            b1 += (double)wb[k] * (double)a[k];
            b2 += (double)wb[k] * (double)a[DKK + k];
        }
        g_beta[0] = b1;
        g_beta[1] = b2;
    }
}

// ---------------- K1: e_src, e_dst via GEMV (double accumulation) ----------------
__global__ void k_edot(const float* __restrict__ X) {
    int warp = (blockIdx.x * blockDim.x + threadIdx.x) >> 5;
    int lane = threadIdx.x & 31;
    const float* xr = X + (size_t)warp * DIMM;
    double a1 = 0.0, a2 = 0.0;
    for (int i = lane; i < DIMM; i += 32) {
        double xv = (double)xr[i];
        a1 += xv * (double)g_u1[i];
        a2 += xv * (double)g_u2[i];
    }
    for (int o = 16; o; o >>= 1) {
        a1 += __shfl_down_sync(0xffffffffu, a1, o);
        a2 += __shfl_down_sync(0xffffffffu, a2, o);
    }
    if (lane == 0) {
        g_s[warp] = (float)(a1 + g_beta[0]);
        g_d[warp] = (float)(a2 + g_beta[1]);
        g_rank[warp] = 0;
    }
}

// ---------------- K2: D = max(d) ----------------
__global__ void k_maxd() {
    __shared__ float sm[1024];
    int t = threadIdx.x;
    float m = -3.4e38f;
    for (int i = t; i < NN; i += 1024) m = fmaxf(m, g_d[i]);
    sm[t] = m;
    __syncthreads();
    for (int s = 512; s; s >>= 1) {
        if (t < s) sm[t] = fmaxf(sm[t], sm[t + s]);
        __syncthreads();
    }
    if (t == 0) g_D = sm[0];
}

// ---------------- K3: ranks (stable counting sort ranks) ----------------
__global__ void k_rank() {
    __shared__ float ds[1024];
    int t = threadIdx.x;
    int kbase = blockIdx.y * 1024;
    for (int i = t; i < 1024; i += 256) ds[i] = g_d[kbase + i];
    __syncthreads();
    int j = blockIdx.x * 256 + t;
    float dj = g_d[j];
    int cnt = 0;
#pragma unroll 4
    for (int i = 0; i < 1024; i++) {
        float dk = ds[i];
        cnt += (dk < dj) || (dk == dj && (kbase + i) < j);
    }
    atomicAdd(&g_rank[j], cnt);
}

// ---------------- K4: scatter sorted d ----------------
__global__ void k_scatterd() {
    int j = blockIdx.x * 256 + threadIdx.x;
    g_sorted[g_rank[j]] = g_d[j];
}

// ---------------- K5: v GEMM (f32x2) + weighted scatter into P1/P2 ----------------
__global__ void __launch_bounds__(256, 1)
k_vgemm(const float* __restrict__ X, const float* __restrict__ Wv,
        const float* __restrict__ bv) {
    __shared__ float As[8][128];
    __shared__ float Bs[8][128];
    const int tid = threadIdx.x;
    const int m0 = blockIdx.y * 128;
    const int n0 = blockIdx.x * 128;
    const int lrow = tid >> 1;
    const int lk4 = (tid & 1) * 4;
    const float* Ap = X + (size_t)(m0 + lrow) * DIMM + lk4;
    const float* Bp = Wv + (size_t)(n0 + lrow) * DIMM + lk4;
    const int tx = tid & 15, ty = tid >> 4;
    const int mm = ty * 8, nn = tx * 8;

    unsigned long long acc[8][4];
#pragma unroll
    for (int i = 0; i < 8; i++)
#pragma unroll
        for (int j = 0; j < 4; j++) acc[i][j] = 0ull;

    for (int kt = 0; kt < DIMM / 8; kt++) {
        float4 av = *(const float4*)(Ap + kt * 8);
        float4 bw = *(const float4*)(Bp + kt * 8);
        As[lk4 + 0][lrow] = av.x; As[lk4 + 1][lrow] = av.y;
        As[lk4 + 2][lrow] = av.z; As[lk4 + 3][lrow] = av.w;
        Bs[lk4 + 0][lrow] = bw.x; Bs[lk4 + 1][lrow] = bw.y;
        Bs[lk4 + 2][lrow] = bw.z; Bs[lk4 + 3][lrow] = bw.w;
        __syncthreads();
#pragma unroll
        for (int k = 0; k < 8; k++) {
            float4 a0 = *(const float4*)&As[k][mm];
            float4 a1 = *(const float4*)&As[k][mm + 4];
            const unsigned long long* b64 = (const unsigned long long*)&Bs[k][nn];
            unsigned long long b0 = b64[0], b1 = b64[1], b2 = b64[2], b3 = b64[3];
            float am[8] = {a0.x, a0.y, a0.z, a0.w, a1.x, a1.y, a1.z, a1.w};
#pragma unroll
            for (int i = 0; i < 8; i++) {
                unsigned long long ai = pack2(am[i], am[i]);
                acc[i][0] = fma2(ai, b0, acc[i][0]);
                acc[i][1] = fma2(ai, b1, acc[i][1]);
                acc[i][2] = fma2(ai, b2, acc[i][2]);
                acc[i][3] = fma2(ai, b3, acc[i][3]);
            }
        }
        __syncthreads();
    }

    // epilogue: bias, weights, scatter by rank
    float Dmax = g_D;
    float bb[8];
#pragma unroll
    for (int u = 0; u < 8; u++) bb[u] = bv[n0 + nn + u];
#pragma unroll
    for (int i = 0; i < 8; i++) {
        int j = m0 + mm + i;
        int r = g_rank[j];
        float dj = g_d[j];
        float w1 = expf(dj - Dmax);
        float w2 = expf(0.01f * dj);
        float v[8];
#pragma unroll
        for (int jp = 0; jp < 4; jp++) unpack2(acc[i][jp], v[2 * jp], v[2 * jp + 1]);
#pragma unroll
        for (int u = 0; u < 8; u++) v[u] += bb[u];
        float* p1 = g_P1 + (size_t)r * DVV + n0 + nn;
        float* p2 = g_P2 + (size_t)r * DVV + n0 + nn;
#pragma unroll
        for (int u = 0; u < 8; u++) {
            p1[u] = w1 * v[u];
            p2[u] = w2 * v[u];
        }
    }
}

// ---------------- K6: per-chunk column sums of P1/P2 ----------------
__global__ void k_chunksum() {
    int c = blockIdx.x, t = threadIdx.x;
    const int RS = DVV / 2;
    const float2* P1 = ((const float2*)g_P1) + (size_t)c * CHUNK * RS + t;
    const float2* P2 = ((const float2*)g_P2) + (size_t)c * CHUNK * RS + t;
    float2 s1 = make_float2(0.f, 0.f), s2 = make_float2(0.f, 0.f);
#pragma unroll 8
    for (int r = 0; r < CHUNK; r++) {
        float2 v1 = P1[(size_t)r * RS];
        float2 v2 = P2[(size_t)r * RS];
        s1.x += v1.x; s1.y += v1.y;
        s2.x += v2.x; s2.y += v2.y;
    }
    ((float2*)g_cs1)[c * RS + t] = s1;
    ((float2*)g_cs2)[c * RS + t] = s2;
}

// ---------------- K7: inter-chunk offsets ----------------
__global__ void k_offsets() {
    int col = blockIdx.x * 256 + threadIdx.x;
    float r2 = 0.f;
    for (int c0 = 0; c0 < NCHUNK; c0 += 8) {
        float v[8];
#pragma unroll
        for (int u = 0; u < 8; u++) v[u] = g_cs2[(c0 + u) * DVV + col];
#pragma unroll
        for (int u = 0; u < 8; u++) { g_off2[(c0 + u) * DVV + col] = r2; r2 += v[u]; }
    }
    g_S2[(size_t)NN * DVV + col] = r2;
    float r1 = 0.f;
    for (int c0 = NCHUNK - 8; c0 >= 0; c0 -= 8) {
        float v[8];
#pragma unroll
        for (int u = 0; u < 8; u++) v[u] = g_cs1[(c0 + u) * DVV + col];
#pragma unroll
        for (int u = 7; u >= 0; u--) { g_off1[(c0 + u) * DVV + col] = r1; r1 += v[u]; }
    }
    g_S1[(size_t)NN * DVV + col] = 0.f;
}

// ---------------- K8: scalar Z scans ----------------
__global__ void k_zscan() {
    __shared__ float s1a[256], s2a[256], o1[256], o2[256];
    int t = threadIdx.x;
    float D = g_D;
    int base = t * 32;
    float l1 = 0.f, l2 = 0.f;
    for (int i = 0; i < 32; i++) {
        float dv = g_sorted[base + i];
        l1 += expf(dv - D);
        l2 += expf(0.01f * dv);
    }
    s1a[t] = l1; s2a[t] = l2;
    __syncthreads();
    if (t == 0) {
        float r = 0.f;
        for (int i = 0; i < 256; i++) { o2[i] = r; r += s2a[i]; }
        g_zpre[NN] = r;
        float r1 = 0.f;
        for (int i = 255; i >= 0; i--) { o1[i] = r1; r1 += s1a[i]; }
        g_zsuf[NN] = 0.f;
    }
    __syncthreads();
    float run2 = o2[t];
    for (int i = 0; i < 32; i++) {
        int p = base + i;
        g_zpre[p] = run2;
        run2 += expf(0.01f * g_sorted[p]);
    }
    float run1 = o1[t];
    for (int i = 31; i >= 0; i--) {
        int p = base + i;
        run1 += expf(g_sorted[p] - D);
        g_zsuf[p] = run1;
    }
}

// ---------------- K9: final scans -> S1 (suffix, incl), S2 (prefix, excl) ----------------
__global__ void k_scan() {
    int c = blockIdx.x, t = threadIdx.x;
    const int RS = DVV / 2;
    float2 run2 = ((const float2*)g_off2)[c * RS + t];
    float2 run1 = ((const float2*)g_off1)[c * RS + t];
    int r0 = c * CHUNK;
    const float2* P1 = (const float2*)g_P1;
    const float2* P2 = (const float2*)g_P2;
    float2* S1 = (float2*)g_S1;
    float2* S2 = (float2*)g_S2;
#pragma unroll 4
    for (int r = 0; r < CHUNK; r++) {
        int pa = r0 + r;
        int pb = r0 + (CHUNK - 1) - r;
        float2 v2 = P2[(size_t)pa * RS + t];
        float2 v1 = P1[(size_t)pb * RS + t];
        S2[(size_t)pa * RS + t] = run2;
        run2.x += v2.x; run2.y += v2.y;
        run1.x += v1.x; run1.y += v1.y;
        S1[(size_t)pb * RS + t] = run1;
    }
}

// ---------------- K10: output rows ----------------
__global__ void k_out(float* __restrict__ out) {
    int i = blockIdx.x;
    float si = g_s[i];
    float target = -si;
    int lo = 0, hi = NN;
    while (lo < hi) {
        int mid = (lo + hi) >> 1;
        if (g_sorted[mid] < target) lo = mid + 1; else hi = mid;
    }
    int k = lo;
    float D = g_D;
    float m = si + D;
    if (m < 0.f) m *= 0.01f;  // lrelu(s_i + D) == row max of lrelu logits
    double c1 = exp((double)si + (double)D - (double)m);   // <= 1
    double c2 = exp(0.01 * (double)si - (double)m);
    double Z = c1 * (double)g_zsuf[k] + c2 * (double)g_zpre[k];
    float f1 = (float)(c1 / Z);
    float f2 = (float)(c2 / Z);
    int t = threadIdx.x;  // 128 threads x float4 = 512 cols
    const float4* S1 = (const float4*)(g_S1 + (size_t)k * DVV);
    const float4* S2 = (const float4*)(g_S2 + (size_t)k * DVV);
    float4 r1 = S1[t], r2 = S2[t];
    float4 o;
    o.x = f1 * r1.x + f2 * r2.x;
    o.y = f1 * r1.y + f2 * r2.y;
    o.z = f1 * r1.z + f2 * r2.z;
    o.w = f1 * r1.w + f2 * r2.w;
    ((float4*)out)[(size_t)i * (DVV / 4) + t] = o;
}

// ---------------- launch ----------------
extern "C" void kernel_launch(void* const* d_in, const int* in_sizes, int n_in,
                              void* d_out, int out_size) {
    (void)in_sizes; (void)n_in; (void)out_size;
    const float* x    = (const float*)d_in[0];
    const float* w_w  = (const float*)d_in[1];
    const float* w_b  = (const float*)d_in[2];
    const float* wv_w = (const float*)d_in[3];
    const float* wv_b = (const float*)d_in[4];
    const float* a    = (const float*)d_in[5];
    float* out = (float*)d_out;

    k_prep<<<2, 256>>>(w_w, w_b, a);
    k_edot<<<NN / 8, 256>>>(x);
    k_maxd<<<1, 1024>>>();
    k_rank<<<dim3(NN / 256, 8), 256>>>();
    k_scatterd<<<NN / 256, 256>>>();
    k_vgemm<<<dim3(DVV / 128, NN / 128), 256>>>(x, wv_w, wv_b);
    k_chunksum<<<NCHUNK, 256>>>();
    k_offsets<<<2, 256>>>();
    k_zscan<<<1, 256>>>();
    k_scan<<<NCHUNK, 256>>>();
    k_out<<<NN, 128>>>(out);
}

// round 3
// speedup vs baseline: 1.4056x; 1.4056x over previous
#include <cuda_runtime.h>
#include <cuda_bf16.h>
#include <math.h>
#include <stdint.h>

#define NN    8192
#define DIMM  512
#define DKK   128
#define DVV   512
#define NCHUNK 256
#define CHUNK  32

// ---------------- scratch (device globals; no allocation) ----------------
__device__ float  g_u1[DIMM], g_u2[DIMM];
__device__ double g_beta[2];
__device__ float  g_s[NN], g_d[NN];
__device__ float  g_D;
__device__ int    g_rank[NN];
__device__ float  g_sorted[NN];
__device__ float  g_w1[NN], g_w2[NN];
__device__ float  g_Vs[(size_t)NN * DVV];
__device__ float  g_S1[(size_t)(NN + 1) * DVV];
__device__ float  g_S2[(size_t)(NN + 1) * DVV];
__device__ float  g_cs1[NCHUNK * DVV], g_cs2[NCHUNK * DVV];
__device__ float  g_off1[NCHUNK * DVV], g_off2[NCHUNK * DVV];
__device__ float  g_zpre[NN + 1], g_zsuf[NN + 1];
__device__ __nv_bfloat16 g_Xhi[(size_t)NN * DIMM];
__device__ __nv_bfloat16 g_Xlo[(size_t)NN * DIMM];
__device__ __nv_bfloat16 g_Wh[(size_t)DVV * DIMM];
__device__ __nv_bfloat16 g_Wl[(size_t)DVV * DIMM];

// ---------------- baseline-PTX helpers (sm_80+: mma.sync / ldmatrix / cp.async) ----
__device__ __forceinline__ uint32_t smem_u32(const void* p) {
    uint32_t a;
    asm("{ .reg .u64 t; cvta.to.shared.u64 t, %1; cvt.u32.u64 %0, t; }" : "=r"(a) : "l"(p));
    return a;
}
__device__ __forceinline__ void cp16(uint32_t saddr, const void* gaddr) {
    asm volatile("cp.async.cg.shared.global [%0], [%1], 16;" :: "r"(saddr), "l"(gaddr) : "memory");
}
#define CP_COMMIT() asm volatile("cp.async.commit_group;" ::: "memory")
#define CP_WAIT(n)  asm volatile("cp.async.wait_group %0;" :: "n"(n) : "memory")

__device__ __forceinline__ void ldsm_x4(uint32_t& r0, uint32_t& r1, uint32_t& r2, uint32_t& r3,
                                        uint32_t addr) {
    asm volatile("ldmatrix.sync.aligned.m8n8.x4.shared.b16 {%0,%1,%2,%3}, [%4];"
                 : "=r"(r0), "=r"(r1), "=r"(r2), "=r"(r3) : "r"(addr));
}
__device__ __forceinline__ void mma16816(float* c, uint32_t a0, uint32_t a1, uint32_t a2,
                                         uint32_t a3, uint32_t b0, uint32_t b1) {
    asm volatile("mma.sync.aligned.m16n8k16.row.col.f32.bf16.bf16.f32 "
                 "{%0,%1,%2,%3}, {%4,%5,%6,%7}, {%8,%9}, {%0,%1,%2,%3};"
                 : "+f"(c[0]), "+f"(c[1]), "+f"(c[2]), "+f"(c[3])
                 : "r"(a0), "r"(a1), "r"(a2), "r"(a3), "r"(b0), "r"(b1));
}

// ---------------- K0: u1 = W^T a1, u2 = W^T a2, betas ----------------
__global__ void k_prep(const float* __restrict__ Ww, const float* __restrict__ wb,
                       const float* __restrict__ a) {
    int d = blockIdx.x * 256 + threadIdx.x;
    double s1 = 0.0, s2 = 0.0;
    for (int k = 0; k < DKK; k++) {
        double w = Ww[(size_t)k * DIMM + d];
        s1 += w * (double)a[k];
        s2 += w * (double)a[DKK + k];
    }
    g_u1[d] = (float)s1;
    g_u2[d] = (float)s2;
    if (d == 0) {
        double b1 = 0.0, b2 = 0.0;
        for (int k = 0; k < DKK; k++) {
            b1 += (double)wb[k] * (double)a[k];
            b2 += (double)wb[k] * (double)a[DKK + k];
        }
        g_beta[0] = b1; g_beta[1] = b2;
    }
}

// ---------------- K1: e_src, e_dst (fp32, warp tree) ----------------
__global__ void k_edot(const float* __restrict__ X) {
    int warp = (blockIdx.x * blockDim.x + threadIdx.x) >> 5;
    int lane = threadIdx.x & 31;
    const float4* xr = (const float4*)(X + (size_t)warp * DIMM);
    const float4* u1 = (const float4*)g_u1;
    const float4* u2 = (const float4*)g_u2;
    float a1 = 0.f, a2 = 0.f;
#pragma unroll
    for (int i = 0; i < 4; i++) {
        int p = lane + 32 * i;
        float4 xv = xr[p], v1 = u1[p], v2 = u2[p];
        a1 += xv.x * v1.x + xv.y * v1.y + xv.z * v1.z + xv.w * v1.w;
        a2 += xv.x * v2.x + xv.y * v2.y + xv.z * v2.z + xv.w * v2.w;
    }
    for (int o = 16; o; o >>= 1) {
        a1 += __shfl_down_sync(0xffffffffu, a1, o);
        a2 += __shfl_down_sync(0xffffffffu, a2, o);
    }
    if (lane == 0) {
        g_s[warp] = (float)((double)a1 + g_beta[0]);
        g_d[warp] = (float)((double)a2 + g_beta[1]);
        g_rank[warp] = 0;
    }
}

// ---------------- K2: D = max(d) ----------------
__global__ void k_maxd() {
    __shared__ float sm[1024];
    int t = threadIdx.x;
    float m = -3.4e38f;
    for (int i = t; i < NN; i += 1024) m = fmaxf(m, g_d[i]);
    sm[t] = m;
    __syncthreads();
    for (int s = 512; s; s >>= 1) {
        if (t < s) sm[t] = fmaxf(sm[t], sm[t + s]);
        __syncthreads();
    }
    if (t == 0) g_D = sm[0];
}

// ---------------- K3: ranks (2 j per thread) ----------------
__global__ void k_rank() {
    __shared__ float ds[512];
    int t = threadIdx.x;
    int kbase = blockIdx.y * 512;
    for (int i = t; i < 512; i += 256) ds[i] = g_d[kbase + i];
    __syncthreads();
    int j0 = blockIdx.x * 512 + t;
    int j1 = j0 + 256;
    float d0 = g_d[j0], d1 = g_d[j1];
    int c0 = 0, c1 = 0;
#pragma unroll 8
    for (int i = 0; i < 512; i++) {
        float dk = ds[i];
        int gi = kbase + i;
        c0 += (dk < d0) || (dk == d0 && gi < j0);
        c1 += (dk < d1) || (dk == d1 && gi < j1);
    }
    atomicAdd(&g_rank[j0], c0);
    atomicAdd(&g_rank[j1], c1);
}

// ---------------- K4: scatter sorted d + weights ----------------
__global__ void k_scatterd() {
    int j = blockIdx.x * 256 + threadIdx.x;
    int r = g_rank[j];
    float dj = g_d[j];
    g_sorted[r] = dj;
    g_w1[r] = expf(dj - g_D);
    g_w2[r] = expf(0.01f * dj);
}

// ---------------- K4b: bf16 hi/lo decomposition of X and Wv ----------------
__global__ void k_cvt(const float* __restrict__ X, const float* __restrict__ Wv) {
    int g = blockIdx.x * 256 + threadIdx.x;
    const int NX = NN * DIMM / 4;
    const float4* src;
    __nv_bfloat16 *dh, *dl;
    int idx;
    if (g < NX) { src = (const float4*)X;  dh = g_Xhi; dl = g_Xlo; idx = g; }
    else        { src = (const float4*)Wv; dh = g_Wh;  dl = g_Wl;  idx = g - NX; }
    float4 v = src[idx];
    __nv_bfloat16 h0 = __float2bfloat16(v.x), h1 = __float2bfloat16(v.y);
    __nv_bfloat16 h2 = __float2bfloat16(v.z), h3 = __float2bfloat16(v.w);
    __nv_bfloat16 l0 = __float2bfloat16(v.x - __bfloat162float(h0));
    __nv_bfloat16 l1 = __float2bfloat16(v.y - __bfloat162float(h1));
    __nv_bfloat16 l2 = __float2bfloat16(v.z - __bfloat162float(h2));
    __nv_bfloat16 l3 = __float2bfloat16(v.w - __bfloat162float(h3));
    __nv_bfloat162* ph = (__nv_bfloat162*)dh;
    __nv_bfloat162* pl = (__nv_bfloat162*)dl;
    ph[idx * 2]     = __nv_bfloat162(h0, h1);
    ph[idx * 2 + 1] = __nv_bfloat162(h2, h3);
    pl[idx * 2]     = __nv_bfloat162(l0, l1);
    pl[idx * 2 + 1] = __nv_bfloat162(l2, l3);
}

// ---------------- K5: warp-MMA V GEMM (bf16 3-split) + rank scatter ----------------
// CTA tile 128x128, 8 warps (4 M x 2 N), warp tile 32x64, k-tile 64,
// cp.async 2-stage, XOR-swizzled SMEM (128B rows, (row&7)<<4).
#define KT 64
#define TILE_BYTES (128 * 128)  // 128 rows x 64 bf16 (128B)
#define SMEM_VG_BYTES (4 * TILE_BYTES)  // A0,A1,B0,B1

__device__ __forceinline__ uint32_t swz(uint32_t row, uint32_t colb) {
    return row * 128u + (colb ^ ((row & 7u) << 4));
}

__global__ void __launch_bounds__(256, 1)
k_vgemm_mma(const float* __restrict__ bv) {
    extern __shared__ char smem[];
    uint32_t sb = smem_u32(smem);
    const int tid = threadIdx.x;
    const int wid = tid >> 5, lane = tid & 31;
    const int wm = wid & 3, wn = wid >> 2;
    const int m0 = blockIdx.y * 128, n0 = blockIdx.x * 128;

    // buffer bases: A0, B0, A1, B1
    const uint32_t sA[2] = { sb, sb + 2 * TILE_BYTES };
    const uint32_t sB[2] = { sb + TILE_BYTES, sb + 3 * TILE_BYTES };

    float acc[2][8][4];
#pragma unroll
    for (int i = 0; i < 2; i++)
#pragma unroll
        for (int j = 0; j < 8; j++)
#pragma unroll
            for (int q = 0; q < 4; q++) acc[i][j][q] = 0.f;

    // load thread mapping: 4 chunks each of A and B per iter
    const int lrow = tid >> 1;          // 0..127
    const int lch0 = (tid & 1) * 4;     // chunk 0..3 or 4..7

    auto issue = [&](int it, int buf) {
        int pass = it >> 3;
        int k0 = (it & 7) * KT;
        const __nv_bfloat16* Ag = (pass == 2) ? g_Xlo : g_Xhi;
        const __nv_bfloat16* Bg = (pass == 1) ? g_Wl : g_Wh;
        const __nv_bfloat16* ga = Ag + (size_t)(m0 + lrow) * DIMM + k0;
        const __nv_bfloat16* gb = Bg + (size_t)(n0 + lrow) * DIMM + k0;
#pragma unroll
        for (int c = 0; c < 4; c++) {
            int ch = lch0 + c;
            cp16(sA[buf] + swz(lrow, ch * 16), ga + ch * 8);
        }
#pragma unroll
        for (int c = 0; c < 4; c++) {
            int ch = lch0 + c;
            cp16(sB[buf] + swz(lrow, ch * 16), gb + ch * 8);
        }
    };

    issue(0, 0);
    CP_COMMIT();

    for (int it = 0; it < 24; it++) {
        int buf = it & 1;
        if (it < 23) {
            issue(it + 1, buf ^ 1);
            CP_COMMIT();
            CP_WAIT(1);
        } else {
            CP_WAIT(0);
        }
        __syncthreads();

#pragma unroll
        for (int ks = 0; ks < 4; ks++) {
            uint32_t colb = ks * 32 + ((lane >> 4) << 4);
            // A fragments: 2 m16 tiles
            uint32_t af[2][4];
#pragma unroll
            for (int mt = 0; mt < 2; mt++) {
                uint32_t row = wm * 32 + mt * 16 + (lane & 15);
                ldsm_x4(af[mt][0], af[mt][1], af[mt][2], af[mt][3], sA[buf] + swz(row, colb));
            }
            // B fragments: 4 x4 loads cover 8 n8 tiles
            uint32_t bf[4][4];
#pragma unroll
            for (int np = 0; np < 4; np++) {
                uint32_t row = wn * 64 + np * 16 + (lane & 15);
                ldsm_x4(bf[np][0], bf[np][1], bf[np][2], bf[np][3], sB[buf] + swz(row, colb));
            }
#pragma unroll
            for (int mt = 0; mt < 2; mt++)
#pragma unroll
                for (int nt = 0; nt < 8; nt++) {
                    int np = nt >> 1, sel = nt & 1;
                    mma16816(acc[mt][nt], af[mt][0], af[mt][1], af[mt][2], af[mt][3],
                             bf[np][0 + sel], bf[np][2 + sel]);
                }
        }
        __syncthreads();
    }

    // epilogue: bias + scatter rows by rank
    const int g = lane >> 2, tg = lane & 3;
#pragma unroll
    for (int mt = 0; mt < 2; mt++) {
        int j0 = m0 + wm * 32 + mt * 16 + g;
        int j1 = j0 + 8;
        int r0 = g_rank[j0], r1 = g_rank[j1];
        float* d0 = g_Vs + (size_t)r0 * DVV;
        float* d1 = g_Vs + (size_t)r1 * DVV;
#pragma unroll
        for (int nt = 0; nt < 8; nt++) {
            int col = n0 + wn * 64 + nt * 8 + 2 * tg;
            float2 bb = *(const float2*)(bv + col);
            float2 o0 = make_float2(acc[mt][nt][0] + bb.x, acc[mt][nt][1] + bb.y);
            float2 o1 = make_float2(acc[mt][nt][2] + bb.x, acc[mt][nt][3] + bb.y);
            *(float2*)(d0 + col) = o0;
            *(float2*)(d1 + col) = o1;
        }
    }
}

// ---------------- K6: per-chunk weighted column sums ----------------
__global__ void k_chunksum() {
    int c = blockIdx.x, t = threadIdx.x;
    const int RS = DVV / 2;
    const float2* V = ((const float2*)g_Vs) + (size_t)c * CHUNK * RS + t;
    float2 s1 = make_float2(0.f, 0.f), s2 = make_float2(0.f, 0.f);
#pragma unroll 8
    for (int r = 0; r < CHUNK; r++) {
        float w1 = g_w1[c * CHUNK + r];
        float w2 = g_w2[c * CHUNK + r];
        float2 v = V[(size_t)r * RS];
        s1.x += w1 * v.x; s1.y += w1 * v.y;
        s2.x += w2 * v.x; s2.y += w2 * v.y;
    }
    ((float2*)g_cs1)[c * RS + t] = s1;
    ((float2*)g_cs2)[c * RS + t] = s2;
}

// ---------------- K7: inter-chunk offsets ----------------
__global__ void k_offsets() {
    int col = blockIdx.x * 256 + threadIdx.x;
    float r2 = 0.f;
    for (int c0 = 0; c0 < NCHUNK; c0 += 8) {
        float v[8];
#pragma unroll
        for (int u = 0; u < 8; u++) v[u] = g_cs2[(c0 + u) * DVV + col];
#pragma unroll
        for (int u = 0; u < 8; u++) { g_off2[(c0 + u) * DVV + col] = r2; r2 += v[u]; }
    }
    g_S2[(size_t)NN * DVV + col] = r2;
    float r1 = 0.f;
    for (int c0 = NCHUNK - 8; c0 >= 0; c0 -= 8) {
        float v[8];
#pragma unroll
        for (int u = 0; u < 8; u++) v[u] = g_cs1[(c0 + u) * DVV + col];
#pragma unroll
        for (int u = 7; u >= 0; u--) { g_off1[(c0 + u) * DVV + col] = r1; r1 += v[u]; }
    }
    g_S1[(size_t)NN * DVV + col] = 0.f;
}

// ---------------- K8: scalar Z scans ----------------
__global__ void k_zscan() {
    __shared__ float s1a[256], s2a[256], o1[256], o2[256];
    int t = threadIdx.x;
    int base = t * 32;
    float l1 = 0.f, l2 = 0.f;
    for (int i = 0; i < 32; i++) { l1 += g_w1[base + i]; l2 += g_w2[base + i]; }
    s1a[t] = l1; s2a[t] = l2;
    __syncthreads();
    if (t == 0) {
        float r = 0.f;
        for (int i = 0; i < 256; i++) { o2[i] = r; r += s2a[i]; }
        g_zpre[NN] = r;
        float r1 = 0.f;
        for (int i = 255; i >= 0; i--) { o1[i] = r1; r1 += s1a[i]; }
        g_zsuf[NN] = 0.f;
    }
    __syncthreads();
    float run2 = o2[t];
    for (int i = 0; i < 32; i++) {
        int p = base + i;
        g_zpre[p] = run2;
        run2 += g_w2[p];
    }
    float run1 = o1[t];
    for (int i = 31; i >= 0; i--) {
        int p = base + i;
        run1 += g_w1[p];
        g_zsuf[p] = run1;
    }
}

// ---------------- K9: final scans -> S1 (suffix incl), S2 (prefix excl) ----------------
__global__ void k_scan() {
    int c = blockIdx.x, t = threadIdx.x;
    const int RS = DVV / 2;
    float2 run2 = ((const float2*)g_off2)[c * RS + t];
    float2 run1 = ((const float2*)g_off1)[c * RS + t];
    int r0 = c * CHUNK;
    const float2* V = (const float2*)g_Vs;
    float2* S1 = (float2*)g_S1;
    float2* S2 = (float2*)g_S2;
#pragma unroll 4
    for (int r = 0; r < CHUNK; r++) {
        int pa = r0 + r;
        int pb = r0 + (CHUNK - 1) - r;
        float2 v2 = V[(size_t)pa * RS + t];
        float2 v1 = V[(size_t)pb * RS + t];
        float w2 = g_w2[pa], w1 = g_w1[pb];
        S2[(size_t)pa * RS + t] = run2;
        run2.x += w2 * v2.x; run2.y += w2 * v2.y;
        run1.x += w1 * v1.x; run1.y += w1 * v1.y;
        S1[(size_t)pb * RS + t] = run1;
    }
}

// ---------------- K10: output rows ----------------
__global__ void k_out(float* __restrict__ out) {
    int i = blockIdx.x;
    float si = g_s[i];
    float target = -si;
    int lo = 0, hi = NN;
    while (lo < hi) {
        int mid = (lo + hi) >> 1;
        if (g_sorted[mid] < target) lo = mid + 1; else hi = mid;
    }
    int k = lo;
    float D = g_D;
    float m = si + D;
    if (m < 0.f) m *= 0.01f;
    double c1 = exp((double)si + (double)D - (double)m);
    double c2 = exp(0.01 * (double)si - (double)m);
    double Z = c1 * (double)g_zsuf[k] + c2 * (double)g_zpre[k];
    float f1 = (float)(c1 / Z);
    float f2 = (float)(c2 / Z);
    int t = threadIdx.x;
    const float4* S1 = (const float4*)(g_S1 + (size_t)k * DVV);
    const float4* S2 = (const float4*)(g_S2 + (size_t)k * DVV);
    float4 r1 = S1[t], r2 = S2[t];
    float4 o;
    o.x = f1 * r1.x + f2 * r2.x;
    o.y = f1 * r1.y + f2 * r2.y;
    o.z = f1 * r1.z + f2 * r2.z;
    o.w = f1 * r1.w + f2 * r2.w;
    ((float4*)out)[(size_t)i * (DVV / 4) + t] = o;
}

// ---------------- launch ----------------
extern "C" void kernel_launch(void* const* d_in, const int* in_sizes, int n_in,
                              void* d_out, int out_size) {
    (void)in_sizes; (void)n_in; (void)out_size;
    const float* x    = (const float*)d_in[0];
    const float* w_w  = (const float*)d_in[1];
    const float* w_b  = (const float*)d_in[2];
    const float* wv_w = (const float*)d_in[3];
    const float* wv_b = (const float*)d_in[4];
    const float* a    = (const float*)d_in[5];
    float* out = (float*)d_out;

    static int smem_set = 0;
    if (!smem_set) {
        cudaFuncSetAttribute(k_vgemm_mma, cudaFuncAttributeMaxDynamicSharedMemorySize,
                             SMEM_VG_BYTES);
        smem_set = 1;
    }

    k_prep<<<2, 256>>>(w_w, w_b, a);
    k_edot<<<NN / 8, 256>>>(x);
    k_maxd<<<1, 1024>>>();
    k_rank<<<dim3(NN / 512, NN / 512), 256>>>();
    k_scatterd<<<NN / 256, 256>>>();
    k_cvt<<<(NN * DIMM + DVV * DIMM) / 4 / 256, 256>>>(x, wv_w);
    k_vgemm_mma<<<dim3(DVV / 128, NN / 128), 256, SMEM_VG_BYTES>>>(wv_b);
    k_chunksum<<<NCHUNK, 256>>>();
    k_offsets<<<2, 256>>>();
    k_zscan<<<1, 256>>>();
    k_scan<<<NCHUNK, 256>>>();
    k_out<<<NN, 128>>>(out);
}

// round 4
// speedup vs baseline: 1.8537x; 1.3188x over previous
#include <cuda_runtime.h>
#include <cuda_fp16.h>
#include <math.h>
#include <stdint.h>

#define NN    8192
#define DIMM  512
#define DKK   128
#define DVV   512
#define NCHUNK 256
#define CHUNK  32

// ---------------- scratch (device globals; no allocation) ----------------
__device__ float  g_u1[DIMM], g_u2[DIMM];
__device__ double g_beta[2];
__device__ float  g_s[NN], g_d[NN];
__device__ float  g_D;
__device__ int    g_rank[NN];
__device__ unsigned long long g_key[NN];
__device__ float  g_sorted[NN];
__device__ float  g_w1[NN], g_w2[NN];
__device__ float  g_Vs[(size_t)NN * DVV];
__device__ float  g_S1[(size_t)(NN + 1) * DVV];
__device__ float  g_S2[(size_t)(NN + 1) * DVV];
__device__ float  g_cs1[NCHUNK * DVV], g_cs2[NCHUNK * DVV];
__device__ float  g_off1[NCHUNK * DVV], g_off2[NCHUNK * DVV];
__device__ float  g_zpre[NN + 1], g_zsuf[NN + 1];
__device__ __half g_Xh[(size_t)NN * DIMM];
__device__ __half g_Xl[(size_t)NN * DIMM];
__device__ __half g_Wh[(size_t)DVV * DIMM];

// ---------------- baseline-PTX helpers (sm_80+: mma.sync / ldmatrix / cp.async) ----
__device__ __forceinline__ uint32_t smem_u32(const void* p) {
    uint32_t a;
    asm("{ .reg .u64 t; cvta.to.shared.u64 t, %1; cvt.u32.u64 %0, t; }" : "=r"(a) : "l"(p));
    return a;
}
__device__ __forceinline__ void cp16(uint32_t saddr, const void* gaddr) {
    asm volatile("cp.async.cg.shared.global [%0], [%1], 16;" :: "r"(saddr), "l"(gaddr) : "memory");
}
#define CP_COMMIT() asm volatile("cp.async.commit_group;" ::: "memory")
#define CP_WAIT(n)  asm volatile("cp.async.wait_group %0;" :: "n"(n) : "memory")

__device__ __forceinline__ void ldsm_x4(uint32_t& r0, uint32_t& r1, uint32_t& r2, uint32_t& r3,
                                        uint32_t addr) {
    asm volatile("ldmatrix.sync.aligned.m8n8.x4.shared.b16 {%0,%1,%2,%3}, [%4];"
                 : "=r"(r0), "=r"(r1), "=r"(r2), "=r"(r3) : "r"(addr));
}
__device__ __forceinline__ void mma16816(float* c, uint32_t a0, uint32_t a1, uint32_t a2,
                                         uint32_t a3, uint32_t b0, uint32_t b1) {
    asm volatile("mma.sync.aligned.m16n8k16.row.col.f32.f16.f16.f32 "
                 "{%0,%1,%2,%3}, {%4,%5,%6,%7}, {%8,%9}, {%0,%1,%2,%3};"
                 : "+f"(c[0]), "+f"(c[1]), "+f"(c[2]), "+f"(c[3])
                 : "r"(a0), "r"(a1), "r"(a2), "r"(a3), "r"(b0), "r"(b1));
}

// ---------------- K0: u1 = W^T a1, u2 = W^T a2, betas ----------------
__global__ void k_prep(const float* __restrict__ Ww, const float* __restrict__ wb,
                       const float* __restrict__ a) {
    int d = blockIdx.x * 256 + threadIdx.x;
    double s1 = 0.0, s2 = 0.0;
    for (int k = 0; k < DKK; k++) {
        double w = Ww[(size_t)k * DIMM + d];
        s1 += w * (double)a[k];
        s2 += w * (double)a[DKK + k];
    }
    g_u1[d] = (float)s1;
    g_u2[d] = (float)s2;
    if (d == 0) {
        double b1 = 0.0, b2 = 0.0;
        for (int k = 0; k < DKK; k++) {
            b1 += (double)wb[k] * (double)a[k];
            b2 += (double)wb[k] * (double)a[DKK + k];
        }
        g_beta[0] = b1; g_beta[1] = b2;
    }
}

// ---------------- K1: e_src, e_dst (fp32, warp tree) + sortable keys ----------------
__global__ void k_edot(const float* __restrict__ X) {
    int warp = (blockIdx.x * blockDim.x + threadIdx.x) >> 5;
    int lane = threadIdx.x & 31;
    const float4* xr = (const float4*)(X + (size_t)warp * DIMM);
    const float4* u1 = (const float4*)g_u1;
    const float4* u2 = (const float4*)g_u2;
    float a1 = 0.f, a2 = 0.f;
#pragma unroll
    for (int i = 0; i < 4; i++) {
        int p = lane + 32 * i;
        float4 xv = xr[p], v1 = u1[p], v2 = u2[p];
        a1 += xv.x * v1.x + xv.y * v1.y + xv.z * v1.z + xv.w * v1.w;
        a2 += xv.x * v2.x + xv.y * v2.y + xv.z * v2.z + xv.w * v2.w;
    }
    for (int o = 16; o; o >>= 1) {
        a1 += __shfl_down_sync(0xffffffffu, a1, o);
        a2 += __shfl_down_sync(0xffffffffu, a2, o);
    }
    if (lane == 0) {
        float dv = (float)((double)a2 + g_beta[1]);
        g_s[warp] = (float)((double)a1 + g_beta[0]);
        g_d[warp] = dv;
        g_rank[warp] = 0;
        uint32_t u = __float_as_uint(dv);
        u ^= (uint32_t)(((int32_t)u >> 31)) | 0x80000000u;  // monotone float->uint
        g_key[warp] = ((unsigned long long)u << 13) | (unsigned long long)warp;
    }
}

// ---------------- K2: D = max(d) ----------------
__global__ void k_maxd() {
    __shared__ float sm[1024];
    int t = threadIdx.x;
    float m = -3.4e38f;
    for (int i = t; i < NN; i += 1024) m = fmaxf(m, g_d[i]);
    sm[t] = m;
    __syncthreads();
    for (int s = 512; s; s >>= 1) {
        if (t < s) sm[t] = fmaxf(sm[t], sm[t + s]);
        __syncthreads();
    }
    if (t == 0) g_D = sm[0];
}

// ---------------- K3: ranks via u64 key compares (2 j per thread) ----------------
__global__ void k_rank() {
    __shared__ unsigned long long ks[512];
    int t = threadIdx.x;
    int kbase = blockIdx.y * 512;
    for (int i = t; i < 512; i += 256) ks[i] = g_key[kbase + i];
    __syncthreads();
    int j0 = blockIdx.x * 512 + t;
    int j1 = j0 + 256;
    unsigned long long kj0 = g_key[j0], kj1 = g_key[j1];
    int c0 = 0, c1 = 0;
#pragma unroll 8
    for (int i = 0; i < 512; i++) {
        unsigned long long kk = ks[i];
        c0 += (kk < kj0);
        c1 += (kk < kj1);
    }
    atomicAdd(&g_rank[j0], c0);
    atomicAdd(&g_rank[j1], c1);
}

// ---------------- K4: scatter sorted d + weights ----------------
__global__ void k_scatterd() {
    int j = blockIdx.x * 256 + threadIdx.x;
    int r = g_rank[j];
    float dj = g_d[j];
    g_sorted[r] = dj;
    g_w1[r] = expf(dj - g_D);
    g_w2[r] = expf(0.01f * dj);
}

// ---------------- K4b: fp16 hi/lo split of X; fp16 of Wv ----------------
__global__ void k_cvt(const float* __restrict__ X, const float* __restrict__ Wv) {
    int g = blockIdx.x * 256 + threadIdx.x;
    const int NX = NN * DIMM / 4;
    if (g < NX) {
        float4 v = ((const float4*)X)[g];
        __half h0 = __float2half_rn(v.x), h1 = __float2half_rn(v.y);
        __half h2 = __float2half_rn(v.z), h3 = __float2half_rn(v.w);
        __half l0 = __float2half_rn(v.x - __half2float(h0));
        __half l1 = __float2half_rn(v.y - __half2float(h1));
        __half l2 = __float2half_rn(v.z - __half2float(h2));
        __half l3 = __float2half_rn(v.w - __half2float(h3));
        __half2* ph = (__half2*)g_Xh;
        __half2* pl = (__half2*)g_Xl;
        ph[g * 2]     = __half2(h0, h1);
        ph[g * 2 + 1] = __half2(h2, h3);
        pl[g * 2]     = __half2(l0, l1);
        pl[g * 2 + 1] = __half2(l2, l3);
    } else {
        int idx = g - NX;
        if (idx < DVV * DIMM / 4) {
            float4 v = ((const float4*)Wv)[idx];
            __half2* pw = (__half2*)g_Wh;
            pw[idx * 2]     = __half2(__float2half_rn(v.x), __float2half_rn(v.y));
            pw[idx * 2 + 1] = __half2(__float2half_rn(v.z), __float2half_rn(v.w));
        }
    }
}

// ---------------- K5: warp-MMA V GEMM (fp16 2-term split) + rank scatter ----------------
// CTA tile 128x128, 8 warps (4 M x 2 N), warp tile 32x64, k-tile 64,
// cp.async 2-stage, XOR-swizzled SMEM. 16 k-iterations: it<8 -> Xh, else Xl; B = Wh.
#define KT 64
#define TILE_BYTES (128 * 128)
#define SMEM_VG_BYTES (4 * TILE_BYTES)

__device__ __forceinline__ uint32_t swz(uint32_t row, uint32_t colb) {
    return row * 128u + (colb ^ ((row & 7u) << 4));
}

__global__ void __launch_bounds__(256)
k_vgemm_mma(const float* __restrict__ bv) {
    extern __shared__ char smem[];
    uint32_t sb = smem_u32(smem);
    const int tid = threadIdx.x;
    const int wid = tid >> 5, lane = tid & 31;
    const int wm = wid & 3, wn = wid >> 2;
    const int m0 = blockIdx.y * 128, n0 = blockIdx.x * 128;

    const uint32_t sA[2] = { sb, sb + 2 * TILE_BYTES };
    const uint32_t sB[2] = { sb + TILE_BYTES, sb + 3 * TILE_BYTES };

    float acc[2][8][4];
#pragma unroll
    for (int i = 0; i < 2; i++)
#pragma unroll
        for (int j = 0; j < 8; j++)
#pragma unroll
            for (int q = 0; q < 4; q++) acc[i][j][q] = 0.f;

    const int lrow = tid >> 1;
    const int lch0 = (tid & 1) * 4;

    auto issue = [&](int it, int buf) {
        int k0 = (it & 7) * KT;
        const __half* Ag = (it < 8) ? g_Xh : g_Xl;
        const __half* ga = Ag + (size_t)(m0 + lrow) * DIMM + k0;
        const __half* gb = g_Wh + (size_t)(n0 + lrow) * DIMM + k0;
#pragma unroll
        for (int c = 0; c < 4; c++) {
            int ch = lch0 + c;
            cp16(sA[buf] + swz(lrow, ch * 16), ga + ch * 8);
        }
#pragma unroll
        for (int c = 0; c < 4; c++) {
            int ch = lch0 + c;
            cp16(sB[buf] + swz(lrow, ch * 16), gb + ch * 8);
        }
    };

    issue(0, 0);
    CP_COMMIT();

    for (int it = 0; it < 16; it++) {
        int buf = it & 1;
        if (it < 15) {
            issue(it + 1, buf ^ 1);
            CP_COMMIT();
            CP_WAIT(1);
        } else {
            CP_WAIT(0);
        }
        __syncthreads();

#pragma unroll
        for (int ks = 0; ks < 4; ks++) {
            uint32_t colb = ks * 32 + ((lane >> 4) << 4);
            uint32_t af[2][4];
#pragma unroll
            for (int mt = 0; mt < 2; mt++) {
                uint32_t row = wm * 32 + mt * 16 + (lane & 15);
                ldsm_x4(af[mt][0], af[mt][1], af[mt][2], af[mt][3], sA[buf] + swz(row, colb));
            }
            uint32_t bf[4][4];
#pragma unroll
            for (int np = 0; np < 4; np++) {
                uint32_t row = wn * 64 + np * 16 + (lane & 15);
                ldsm_x4(bf[np][0], bf[np][1], bf[np][2], bf[np][3], sB[buf] + swz(row, colb));
            }
#pragma unroll
            for (int mt = 0; mt < 2; mt++)
#pragma unroll
                for (int nt = 0; nt < 8; nt++) {
                    int np = nt >> 1, sel = nt & 1;
                    mma16816(acc[mt][nt], af[mt][0], af[mt][1], af[mt][2], af[mt][3],
                             bf[np][0 + sel], bf[np][2 + sel]);
                }
        }
        __syncthreads();
    }

    // epilogue: bias + scatter rows by rank
    const int g = lane >> 2, tg = lane & 3;
#pragma unroll
    for (int mt = 0; mt < 2; mt++) {
        int j0 = m0 + wm * 32 + mt * 16 + g;
        int j1 = j0 + 8;
        int r0 = g_rank[j0], r1 = g_rank[j1];
        float* d0 = g_Vs + (size_t)r0 * DVV;
        float* d1 = g_Vs + (size_t)r1 * DVV;
#pragma unroll
        for (int nt = 0; nt < 8; nt++) {
            int col = n0 + wn * 64 + nt * 8 + 2 * tg;
            float2 bb = *(const float2*)(bv + col);
            float2 o0 = make_float2(acc[mt][nt][0] + bb.x, acc[mt][nt][1] + bb.y);
            float2 o1 = make_float2(acc[mt][nt][2] + bb.x, acc[mt][nt][3] + bb.y);
            *(float2*)(d0 + col) = o0;
            *(float2*)(d1 + col) = o1;
        }
    }
}

// ---------------- K6: per-chunk weighted column sums ----------------
__global__ void k_chunksum() {
    int c = blockIdx.x, t = threadIdx.x;
    const int RS = DVV / 2;
    const float2* V = ((const float2*)g_Vs) + (size_t)c * CHUNK * RS + t;
    float2 s1 = make_float2(0.f, 0.f), s2 = make_float2(0.f, 0.f);
#pragma unroll 8
    for (int r = 0; r < CHUNK; r++) {
        float w1 = g_w1[c * CHUNK + r];
        float w2 = g_w2[c * CHUNK + r];
        float2 v = V[(size_t)r * RS];
        s1.x += w1 * v.x; s1.y += w1 * v.y;
        s2.x += w2 * v.x; s2.y += w2 * v.y;
    }
    ((float2*)g_cs1)[c * RS + t] = s1;
    ((float2*)g_cs2)[c * RS + t] = s2;
}

// ---------------- K7: inter-chunk offsets + scalar Z scans (fused) ----------------
__global__ void k_offz() {
    if (blockIdx.x < 2) {
        int col = blockIdx.x * 256 + threadIdx.x;
        float r2 = 0.f;
        for (int c0 = 0; c0 < NCHUNK; c0 += 8) {
            float v[8];
#pragma unroll
            for (int u = 0; u < 8; u++) v[u] = g_cs2[(c0 + u) * DVV + col];
#pragma unroll
            for (int u = 0; u < 8; u++) { g_off2[(c0 + u) * DVV + col] = r2; r2 += v[u]; }
        }
        g_S2[(size_t)NN * DVV + col] = r2;
        float r1 = 0.f;
        for (int c0 = NCHUNK - 8; c0 >= 0; c0 -= 8) {
            float v[8];
#pragma unroll
            for (int u = 0; u < 8; u++) v[u] = g_cs1[(c0 + u) * DVV + col];
#pragma unroll
            for (int u = 7; u >= 0; u--) { g_off1[(c0 + u) * DVV + col] = r1; r1 += v[u]; }
        }
        g_S1[(size_t)NN * DVV + col] = 0.f;
    } else {
        __shared__ float s1a[256], s2a[256], o1[256], o2[256];
        int t = threadIdx.x;
        int base = t * 32;
        float l1 = 0.f, l2 = 0.f;
        for (int i = 0; i < 32; i++) { l1 += g_w1[base + i]; l2 += g_w2[base + i]; }
        s1a[t] = l1; s2a[t] = l2;
        __syncthreads();
        if (t == 0) {
            float r = 0.f;
            for (int i = 0; i < 256; i++) { o2[i] = r; r += s2a[i]; }
            g_zpre[NN] = r;
            float r1 = 0.f;
            for (int i = 255; i >= 0; i--) { o1[i] = r1; r1 += s1a[i]; }
            g_zsuf[NN] = 0.f;
        }
        __syncthreads();
        float run2 = o2[t];
        for (int i = 0; i < 32; i++) {
            int p = base + i;
            g_zpre[p] = run2;
            run2 += g_w2[p];
        }
        float run1 = o1[t];
        for (int i = 31; i >= 0; i--) {
            int p = base + i;
            run1 += g_w1[p];
            g_zsuf[p] = run1;
        }
    }
}

// ---------------- K9: final scans -> S1 (suffix incl), S2 (prefix excl) ----------------
__global__ void k_scan() {
    int c = blockIdx.x, t = threadIdx.x;
    const int RS = DVV / 2;
    float2 run2 = ((const float2*)g_off2)[c * RS + t];
    float2 run1 = ((const float2*)g_off1)[c * RS + t];
    int r0 = c * CHUNK;
    const float2* V = (const float2*)g_Vs;
    float2* S1 = (float2*)g_S1;
    float2* S2 = (float2*)g_S2;
#pragma unroll 4
    for (int r = 0; r < CHUNK; r++) {
        int pa = r0 + r;
        int pb = r0 + (CHUNK - 1) - r;
        float2 v2 = V[(size_t)pa * RS + t];
        float2 v1 = V[(size_t)pb * RS + t];
        float w2 = g_w2[pa], w1 = g_w1[pb];
        S2[(size_t)pa * RS + t] = run2;
        run2.x += w2 * v2.x; run2.y += w2 * v2.y;
        run1.x += w1 * v1.x; run1.y += w1 * v1.y;
        S1[(size_t)pb * RS + t] = run1;
    }
}

// ---------------- K10: output rows ----------------
__global__ void k_out(float* __restrict__ out) {
    int i = blockIdx.x;
    float si = g_s[i];
    float target = -si;
    int lo = 0, hi = NN;
    while (lo < hi) {
        int mid = (lo + hi) >> 1;
        if (g_sorted[mid] < target) lo = mid + 1; else hi = mid;
    }
    int k = lo;
    float D = g_D;
    float m = si + D;
    if (m < 0.f) m *= 0.01f;
    double c1 = exp((double)si + (double)D - (double)m);
    double c2 = exp(0.01 * (double)si - (double)m);
    double Z = c1 * (double)g_zsuf[k] + c2 * (double)g_zpre[k];
    float f1 = (float)(c1 / Z);
    float f2 = (float)(c2 / Z);
    int t = threadIdx.x;
    const float4* S1 = (const float4*)(g_S1 + (size_t)k * DVV);
    const float4* S2 = (const float4*)(g_S2 + (size_t)k * DVV);
    float4 r1 = S1[t], r2 = S2[t];
    float4 o;
    o.x = f1 * r1.x + f2 * r2.x;
    o.y = f1 * r1.y + f2 * r2.y;
    o.z = f1 * r1.z + f2 * r2.z;
    o.w = f1 * r1.w + f2 * r2.w;
    ((float4*)out)[(size_t)i * (DVV / 4) + t] = o;
}

// ---------------- launch ----------------
extern "C" void kernel_launch(void* const* d_in, const int* in_sizes, int n_in,
                              void* d_out, int out_size) {
    (void)in_sizes; (void)n_in; (void)out_size;
    const float* x    = (const float*)d_in[0];
    const float* w_w  = (const float*)d_in[1];
    const float* w_b  = (const float*)d_in[2];
    const float* wv_w = (const float*)d_in[3];
    const float* wv_b = (const float*)d_in[4];
    const float* a    = (const float*)d_in[5];
    float* out = (float*)d_out;

    static int smem_set = 0;
    if (!smem_set) {
        cudaFuncSetAttribute(k_vgemm_mma, cudaFuncAttributeMaxDynamicSharedMemorySize,
                             SMEM_VG_BYTES);
        smem_set = 1;
    }

    const int CVT_BLOCKS = (NN * DIMM / 4 + DVV * DIMM / 4 + 255) / 256;

    k_prep<<<2, 256>>>(w_w, w_b, a);
    k_edot<<<NN / 8, 256>>>(x);
    k_maxd<<<1, 1024>>>();
    k_rank<<<dim3(NN / 512, NN / 512), 256>>>();
    k_scatterd<<<NN / 256, 256>>>();
    k_cvt<<<CVT_BLOCKS, 256>>>(x, wv_w);
    k_vgemm_mma<<<dim3(DVV / 128, NN / 128), 256, SMEM_VG_BYTES>>>(wv_b);
    k_chunksum<<<NCHUNK, 256>>>();
    k_offz<<<3, 256>>>();
    k_scan<<<NCHUNK, 256>>>();
    k_out<<<NN, 128>>>(out);
}